// round 2
// baseline (speedup 1.0000x reference)
#include <cuda_runtime.h>
#include <stdint.h>

// ---------------- problem constants ----------------
#define T_STEPS 16
#define NNODES  50000
#define IN_F    128
#define B_N     4096
#define S1_N    5
#define S2_N    2
#define H1_N    128
#define H2_N    64
#define C_OUT   32
#define K_CONV  5
#define R1      (B_N + B_N * S1_N)   // 24576 layer-1 rows per timestep

// ---------------- scratch (static device memory; no allocations) ----------------
__device__ uint8_t g_s1[(size_t)T_STEPS * R1 * H1_N];     // ~50 MB layer-1 spikes
__device__ uint8_t g_s2[(size_t)T_STEPS * B_N * H2_N];    // ~4 MB  layer-2 spikes
__device__ float   g_A[H2_N * T_STEPS];                   // folded delay+conv weights

// ============================================================================
// Kernel 0: fold softmax(delay_w), depthwise-conv SAME coefficients and the
// time-mean into a single A[c][t] matrix.
//   M[b,c] = sum_t s2[b,t,c] * A[c,t]
//   A[c,t] = sum_di w[g(c),di] * coef[c, t + d_di]   (t + d <= T-1)
//   coef[c,tau] = (1/T) * sum_{k in [max(0,tau-13), min(4,tau+2)]} ker[c,k]
// ============================================================================
__global__ void prepA_kernel(const float* __restrict__ delay_w,
                             const float* __restrict__ dwk) {
    int c = threadIdx.x;
    if (c >= H2_N) return;
    int g = c >> 3;  // GROUPS=8, group size 8
    float w0 = delay_w[g * 3 + 0];
    float w1 = delay_w[g * 3 + 1];
    float w2 = delay_w[g * 3 + 2];
    float mx = fmaxf(w0, fmaxf(w1, w2));
    float e0 = expf(w0 - mx), e1 = expf(w1 - mx), e2 = expf(w2 - mx);
    float inv = 1.0f / (e0 + e1 + e2);
    e0 *= inv; e1 *= inv; e2 *= inv;

    float coef[T_STEPS];
    #pragma unroll
    for (int tau = 0; tau < T_STEPS; tau++) {
        int kmin = (tau - 13 > 0) ? (tau - 13) : 0;
        int kmax = (tau + 2 < 4) ? (tau + 2) : 4;
        float s = 0.0f;
        for (int k = kmin; k <= kmax; k++) s += dwk[c * K_CONV + k];
        coef[tau] = s * (1.0f / (float)T_STEPS);
    }
    #pragma unroll
    for (int t = 0; t < T_STEPS; t++) {
        float a = 0.0f;
        if (t + 1 < T_STEPS) a += e0 * coef[t + 1];
        if (t + 3 < T_STEPS) a += e1 * coef[t + 3];
        if (t + 5 < T_STEPS) a += e2 * coef[t + 5];
        g_A[c * T_STEPS + t] = a;
    }
}

// ============================================================================
// Kernel 1: fused gather + mean + dual GEMM + LIF spike (TAU=1 -> stateless).
// Block: 64 rows x 128 output channels, K = 256 ([self | neigh_mean]).
// Rows [0,B): self = xt[nodes[i]], neigh = mean of 5 nbr1 rows.
// Rows [B,R1): self = xt[nbr1_flat[j]], neigh = mean of 2 nbr2 rows.
// Dyn smem: Zt[256][64] (k-major inputs) + Wt[64][128] tile = 96 KB.
// ============================================================================
__global__ void __launch_bounds__(256, 2)
layer1_kernel(const float* __restrict__ x, const int* __restrict__ nodes,
              const int* __restrict__ nbr1, const int* __restrict__ nbr2,
              const float* __restrict__ W1s, const float* __restrict__ W1n,
              const float* __restrict__ b1) {
    extern __shared__ float sm[];
    float* Zt = sm;                 // 256 * 64
    float* Wt = sm + 256 * 64;      // 64 * 128
    __shared__ int s_self[64];
    __shared__ int s_nbr[64 * S1_N];

    const int tid = threadIdx.x;
    const int t = blockIdx.y;
    const int blk = blockIdx.x;           // 0..383
    const bool typeA = (blk < (B_N / 64));
    const int rowbase = blk * 64;

    // ---- index stage ----
    if (typeA) {
        if (tid < 64) s_self[tid] = nodes[rowbase + tid];
        for (int q = tid; q < 64 * S1_N; q += 256) {
            int r = q / S1_N, s = q - r * S1_N;
            s_nbr[q] = nbr1[((size_t)t * B_N + rowbase + r) * S1_N + s];
        }
    } else {
        const int j0 = rowbase - B_N;     // index into flattened (B*S1)
        if (tid < 64) s_self[tid] = nbr1[(size_t)t * B_N * S1_N + j0 + tid];
        for (int q = tid; q < 64 * S2_N; q += 256) {
            int r = q >> 1, s = q & 1;
            s_nbr[q] = nbr2[((size_t)t * (B_N * S1_N) + j0 + r) * S2_N + s];
        }
    }
    __syncthreads();

    // ---- gather stage: build Zt (k-major) ----
    const float* xt = x + (size_t)t * NNODES * IN_F;
    const int r  = tid & 63;
    const int w0 = tid >> 6;              // 0..3
    for (int w = w0; w < 32; w += 4) {    // self features
        float4 v = *(const float4*)(xt + (size_t)s_self[r] * IN_F + w * 4);
        int k = w * 4;
        Zt[(k + 0) * 64 + r] = v.x;
        Zt[(k + 1) * 64 + r] = v.y;
        Zt[(k + 2) * 64 + r] = v.z;
        Zt[(k + 3) * 64 + r] = v.w;
    }
    const int   S    = typeA ? S1_N : S2_N;
    const float invS = typeA ? 0.2f : 0.5f;
    for (int w = w0; w < 32; w += 4) {    // neighbor-mean features
        float ax = 0.f, ay = 0.f, az = 0.f, aw = 0.f;
        for (int s = 0; s < S; s++) {
            float4 v = *(const float4*)(xt + (size_t)s_nbr[r * S + s] * IN_F + w * 4);
            ax += v.x; ay += v.y; az += v.z; aw += v.w;
        }
        int k = IN_F + w * 4;
        Zt[(k + 0) * 64 + r] = ax * invS;
        Zt[(k + 1) * 64 + r] = ay * invS;
        Zt[(k + 2) * 64 + r] = az * invS;
        Zt[(k + 3) * 64 + r] = aw * invS;
    }

    // ---- GEMM: 64x128, K=256, micro-tile 4 rows x 8 cols ----
    float acc[4][8];
    #pragma unroll
    for (int i = 0; i < 4; i++)
        #pragma unroll
        for (int j = 0; j < 8; j++) acc[i][j] = 0.0f;

    const int r0 = (tid & 15) * 4;   // 16 row-groups
    const int c0 = (tid >> 4) * 8;   // 16 col-groups

    for (int kt = 0; kt < 4; kt++) {
        __syncthreads();  // protect Zt (first iter) / Wt reuse (later iters)
        for (int idx = tid; idx < 64 * 32; idx += 256) {
            int kr = idx >> 5, c4 = idx & 31;
            int kg = kt * 64 + kr;
            const float* src = (kg < IN_F) ? (W1s + (size_t)kg * H1_N)
                                           : (W1n + (size_t)(kg - IN_F) * H1_N);
            *(float4*)&Wt[kr * 128 + c4 * 4] = *(const float4*)(src + c4 * 4);
        }
        __syncthreads();
        #pragma unroll 8
        for (int k = 0; k < 64; k++) {
            float4 a4 = *(const float4*)&Zt[(kt * 64 + k) * 64 + r0];
            float4 bA = *(const float4*)&Wt[k * 128 + c0];
            float4 bB = *(const float4*)&Wt[k * 128 + c0 + 4];
            float av[4] = {a4.x, a4.y, a4.z, a4.w};
            float bv[8] = {bA.x, bA.y, bA.z, bA.w, bB.x, bB.y, bB.z, bB.w};
            #pragma unroll
            for (int i = 0; i < 4; i++)
                #pragma unroll
                for (int j = 0; j < 8; j++)
                    acc[i][j] = fmaf(av[i], bv[j], acc[i][j]);
        }
    }

    // ---- epilogue: u = acc + b1; spike = (u >= VTH); packed byte store ----
    #pragma unroll
    for (int i = 0; i < 4; i++) {
        int row = rowbase + r0 + i;
        unsigned long long pk = 0ull;
        #pragma unroll
        for (int j = 0; j < 8; j++) {
            float u = acc[i][j] + b1[c0 + j];
            if (u >= 1.0f) pk |= (1ull << (8 * j));
        }
        *(unsigned long long*)(g_s1 + ((size_t)t * R1 + row) * H1_N + c0) = pk;
    }
}

// ============================================================================
// Kernel 2: layer-2 GEMM. u2 = [g0 | mean(g1)] @ [W2s; W2n] + b2, spike.
// Block: 64 rows x 64 cols, K=256. Packed-byte summation for the 5-way mean.
// Dyn smem: Zt[256][64] + Wt[256][64] = 128 KB.
// ============================================================================
__global__ void __launch_bounds__(256, 1)
layer2_kernel(const float* __restrict__ W2s, const float* __restrict__ W2n,
              const float* __restrict__ b2) {
    extern __shared__ float sm[];
    float* Zt = sm;                  // 256 * 64
    float* Wt = sm + 256 * 64;       // 256 * 64
    const int tid = threadIdx.x;
    const int t = blockIdx.y;
    const int b0 = blockIdx.x * 64;

    const uint8_t* s1t = g_s1 + (size_t)t * R1 * H1_N;
    const int r  = tid & 63;
    const int w0 = tid >> 6;
    for (int w = w0; w < 32; w += 4) {
        uint32_t gw = *(const uint32_t*)(s1t + (size_t)(b0 + r) * H1_N + w * 4);
        uint32_t mw = 0;   // bytes are 0/1; sum of 5 fits in a byte
        #pragma unroll
        for (int s = 0; s < S1_N; s++)
            mw += *(const uint32_t*)(s1t + (size_t)(B_N + (b0 + r) * S1_N + s) * H1_N + w * 4);
        int k = w * 4;
        Zt[(k + 0) * 64 + r] = (float)(gw & 0xffu);
        Zt[(k + 1) * 64 + r] = (float)((gw >> 8) & 0xffu);
        Zt[(k + 2) * 64 + r] = (float)((gw >> 16) & 0xffu);
        Zt[(k + 3) * 64 + r] = (float)(gw >> 24);
        Zt[(H1_N + k + 0) * 64 + r] = 0.2f * (float)(mw & 0xffu);
        Zt[(H1_N + k + 1) * 64 + r] = 0.2f * (float)((mw >> 8) & 0xffu);
        Zt[(H1_N + k + 2) * 64 + r] = 0.2f * (float)((mw >> 16) & 0xffu);
        Zt[(H1_N + k + 3) * 64 + r] = 0.2f * (float)(mw >> 24);
    }
    for (int idx = tid; idx < 256 * 16; idx += 256) {
        int kr = idx >> 4, c4 = idx & 15;
        const float* src = (kr < H1_N) ? (W2s + (size_t)kr * H2_N)
                                       : (W2n + (size_t)(kr - H1_N) * H2_N);
        *(float4*)&Wt[kr * 64 + c4 * 4] = *(const float4*)(src + c4 * 4);
    }
    __syncthreads();

    float acc[4][4];
    #pragma unroll
    for (int i = 0; i < 4; i++)
        #pragma unroll
        for (int j = 0; j < 4; j++) acc[i][j] = 0.0f;

    const int r0 = (tid & 15) * 4;
    const int c0 = (tid >> 4) * 4;
    #pragma unroll 8
    for (int k = 0; k < 256; k++) {
        float4 a4 = *(const float4*)&Zt[k * 64 + r0];
        float4 b4 = *(const float4*)&Wt[k * 64 + c0];
        float av[4] = {a4.x, a4.y, a4.z, a4.w};
        float bv[4] = {b4.x, b4.y, b4.z, b4.w};
        #pragma unroll
        for (int i = 0; i < 4; i++)
            #pragma unroll
            for (int j = 0; j < 4; j++)
                acc[i][j] = fmaf(av[i], bv[j], acc[i][j]);
    }

    #pragma unroll
    for (int i = 0; i < 4; i++) {
        int b = b0 + r0 + i;
        uint32_t pk = 0;
        #pragma unroll
        for (int j = 0; j < 4; j++) {
            float u = acc[i][j] + b2[c0 + j];
            if (u >= 1.0f) pk |= (1u << (8 * j));
        }
        *(uint32_t*)(g_s2 + ((size_t)t * B_N + b) * H2_N + c0) = pk;
    }
}

// ============================================================================
// Kernel 3: readout. out[b,j] = ro_b[j] + sum_c (sum_t s2[t,b,c]*A[c,t]) ro_W[c,j]
// One warp per batch row.
// ============================================================================
__global__ void __launch_bounds__(256)
readout_kernel(const float* __restrict__ ro_W, const float* __restrict__ ro_b,
               float* __restrict__ out) {
    __shared__ float Msm[8][64];
    const int warp = threadIdx.x >> 5;
    const int lane = threadIdx.x & 31;
    const int b = blockIdx.x * 8 + warp;

    float m0 = 0.f, m1 = 0.f;
    #pragma unroll
    for (int t = 0; t < T_STEPS; t++) {
        const uint8_t* row = g_s2 + ((size_t)t * B_N + b) * H2_N;
        m0 = fmaf((float)row[lane],      g_A[lane * T_STEPS + t],        m0);
        m1 = fmaf((float)row[lane + 32], g_A[(lane + 32) * T_STEPS + t], m1);
    }
    Msm[warp][lane] = m0;
    Msm[warp][lane + 32] = m1;
    __syncwarp();

    float o = ro_b[lane];
    #pragma unroll
    for (int c = 0; c < 64; c++)
        o = fmaf(Msm[warp][c], ro_W[c * C_OUT + lane], o);
    out[(size_t)b * C_OUT + lane] = o;
}

// ============================================================================
extern "C" void kernel_launch(void* const* d_in, const int* in_sizes, int n_in,
                              void* d_out, int out_size) {
    const float* x    = (const float*)d_in[0];
    const int*   nodes= (const int*)  d_in[1];
    const int*   nbr1 = (const int*)  d_in[2];
    const int*   nbr2 = (const int*)  d_in[3];
    const float* W1s  = (const float*)d_in[4];
    const float* W1n  = (const float*)d_in[5];
    const float* b1   = (const float*)d_in[6];
    const float* W2s  = (const float*)d_in[7];
    const float* W2n  = (const float*)d_in[8];
    const float* b2   = (const float*)d_in[9];
    const float* dlw  = (const float*)d_in[10];
    const float* dwk  = (const float*)d_in[11];
    const float* roW  = (const float*)d_in[12];
    const float* rob  = (const float*)d_in[13];
    float* out = (float*)d_out;

    cudaFuncSetAttribute(layer1_kernel, cudaFuncAttributeMaxDynamicSharedMemorySize, 98304);
    cudaFuncSetAttribute(layer2_kernel, cudaFuncAttributeMaxDynamicSharedMemorySize, 131072);

    prepA_kernel<<<1, 64>>>(dlw, dwk);
    layer1_kernel<<<dim3(R1 / 64, T_STEPS), 256, 98304>>>(x, nodes, nbr1, nbr2, W1s, W1n, b1);
    layer2_kernel<<<dim3(B_N / 64, T_STEPS), 256, 131072>>>(W2s, W2n, b2);
    readout_kernel<<<B_N / 8, 256>>>(roW, rob, out);
}

// round 3
// speedup vs baseline: 1.0681x; 1.0681x over previous
#include <cuda_runtime.h>
#include <stdint.h>

// ---------------- problem constants ----------------
#define T_STEPS 16
#define NNODES  50000
#define IN_F    128
#define B_N     4096
#define S1_N    5
#define S2_N    2
#define H1_N    128
#define H2_N    64
#define C_OUT   32
#define K_CONV  5
#define R1      (B_N + B_N * S1_N)   // 24576 layer-1 rows per timestep

typedef unsigned long long ull;

// ---------------- scratch (static device memory; no allocations) ----------------
__device__ uint8_t g_s1[(size_t)T_STEPS * R1 * H1_N];     // ~50 MB layer-1 spikes
__device__ uint8_t g_s2[(size_t)T_STEPS * B_N * H2_N];    // ~4 MB  layer-2 spikes
__device__ float   g_A[H2_N * T_STEPS];                   // folded delay+conv weights

// ---------------- packed fp32x2 helpers (sm_100+) ----------------
__device__ __forceinline__ ull fma2(ull a, ull b, ull c) {
    ull d;
    asm("fma.rn.f32x2 %0, %1, %2, %3;" : "=l"(d) : "l"(a), "l"(b), "l"(c));
    return d;
}
__device__ __forceinline__ ull dup2(float v) {
    ull r;
    asm("mov.b64 %0, {%1, %1};" : "=l"(r) : "f"(v));
    return r;
}
__device__ __forceinline__ float lo2(ull v) { return __uint_as_float((unsigned)(v)); }
__device__ __forceinline__ float hi2(ull v) { return __uint_as_float((unsigned)(v >> 32)); }

// ============================================================================
// Kernel 0: fold softmax(delay_w) + depthwise-conv SAME + time-mean into A[c][t].
// ============================================================================
__global__ void prepA_kernel(const float* __restrict__ delay_w,
                             const float* __restrict__ dwk) {
    int c = threadIdx.x;
    if (c >= H2_N) return;
    int g = c >> 3;  // GROUPS=8
    float w0 = delay_w[g * 3 + 0];
    float w1 = delay_w[g * 3 + 1];
    float w2 = delay_w[g * 3 + 2];
    float mx = fmaxf(w0, fmaxf(w1, w2));
    float e0 = expf(w0 - mx), e1 = expf(w1 - mx), e2 = expf(w2 - mx);
    float inv = 1.0f / (e0 + e1 + e2);
    e0 *= inv; e1 *= inv; e2 *= inv;

    float coef[T_STEPS];
    #pragma unroll
    for (int tau = 0; tau < T_STEPS; tau++) {
        int kmin = (tau - 13 > 0) ? (tau - 13) : 0;
        int kmax = (tau + 2 < 4) ? (tau + 2) : 4;
        float s = 0.0f;
        for (int k = kmin; k <= kmax; k++) s += dwk[c * K_CONV + k];
        coef[tau] = s * (1.0f / (float)T_STEPS);
    }
    #pragma unroll
    for (int t = 0; t < T_STEPS; t++) {
        float a = 0.0f;
        if (t + 1 < T_STEPS) a += e0 * coef[t + 1];
        if (t + 3 < T_STEPS) a += e1 * coef[t + 3];
        if (t + 5 < T_STEPS) a += e2 * coef[t + 5];
        g_A[c * T_STEPS + t] = a;
    }
}

// ============================================================================
// Kernel 1: fused gather + mean + dual GEMM + spike, packed fp32x2 mainloop.
// Block: 128 rows x 128 cols, K=256 in 4 chunks of 64.
//   chunks 0,1 = self features [0:64),[64:128) through [W1s]
//   chunks 2,3 = neigh-mean features through [W1n]
// Micro-tile: 8 rows x 8 cols per thread as 4 row-pairs (f32x2).
// Dyn smem: Zt[64][128] + Wt[64][128] = 64 KB -> 2 blocks/SM.
// ============================================================================
__global__ void __launch_bounds__(256, 2)
layer1_kernel(const float* __restrict__ x, const int* __restrict__ nodes,
              const int* __restrict__ nbr1, const int* __restrict__ nbr2,
              const float* __restrict__ W1s, const float* __restrict__ W1n,
              const float* __restrict__ b1) {
    extern __shared__ float sm[];
    float* Zt = sm;                 // [64][128] k-major
    float* Wt = sm + 64 * 128;      // [64][128]
    __shared__ int s_self[128];
    __shared__ int s_nbr[128 * S1_N];

    const int tid = threadIdx.x;
    const int t = blockIdx.y;
    const int blk = blockIdx.x;               // 0..191
    const bool typeA = (blk < (B_N / 128));   // first 32 blocks
    const int rowbase = blk * 128;

    // ---- index stage ----
    if (typeA) {
        if (tid < 128) s_self[tid] = nodes[rowbase + tid];
        for (int q = tid; q < 128 * S1_N; q += 256) {
            int r = q / S1_N, s = q - r * S1_N;
            s_nbr[q] = nbr1[((size_t)t * B_N + rowbase + r) * S1_N + s];
        }
    } else {
        const int j0 = rowbase - B_N;         // into flattened (B*S1)
        if (tid < 128) s_self[tid] = nbr1[(size_t)t * B_N * S1_N + j0 + tid];
        for (int q = tid; q < 128 * S2_N; q += 256) {
            int r = q >> 1, s = q & 1;
            s_nbr[q] = nbr2[((size_t)t * (B_N * S1_N) + j0 + r) * S2_N + s];
        }
    }

    const float* xt = x + (size_t)t * NNODES * IN_F;
    const int gr = tid >> 1;                  // gather row 0..127
    const int gw0 = (tid & 1) * 8;            // 8 float4 groups per half

    const int r0 = (tid & 15) * 8;            // 16 row-groups x 8 rows
    const int c0 = (tid >> 4) * 8;            // 16 col-groups x 8 cols

    ull acc[4][8];                            // 4 row-pairs x 8 cols
    #pragma unroll
    for (int i = 0; i < 4; i++)
        #pragma unroll
        for (int j = 0; j < 8; j++) acc[i][j] = 0ull;

    for (int kt = 0; kt < 4; kt++) {
        __syncthreads();   // Zt/Wt free (and index stage visible on iter 0)
        const int f0 = (kt & 1) * 64;
        // ---- gather Zt chunk (k-major) ----
        if (kt < 2) {
            const float* src = xt + (size_t)s_self[gr] * IN_F + f0;
            #pragma unroll
            for (int w = 0; w < 8; w++) {
                float4 v = *(const float4*)(src + (gw0 + w) * 4);
                int k = (gw0 + w) * 4;
                Zt[(k + 0) * 128 + gr] = v.x;
                Zt[(k + 1) * 128 + gr] = v.y;
                Zt[(k + 2) * 128 + gr] = v.z;
                Zt[(k + 3) * 128 + gr] = v.w;
            }
        } else if (typeA) {
            #pragma unroll
            for (int w = 0; w < 8; w++) {
                float ax = 0.f, ay = 0.f, az = 0.f, aw = 0.f;
                #pragma unroll
                for (int s = 0; s < S1_N; s++) {
                    float4 v = *(const float4*)(xt + (size_t)s_nbr[gr * S1_N + s] * IN_F
                                                + f0 + (gw0 + w) * 4);
                    ax += v.x; ay += v.y; az += v.z; aw += v.w;
                }
                int k = (gw0 + w) * 4;
                Zt[(k + 0) * 128 + gr] = ax * 0.2f;
                Zt[(k + 1) * 128 + gr] = ay * 0.2f;
                Zt[(k + 2) * 128 + gr] = az * 0.2f;
                Zt[(k + 3) * 128 + gr] = aw * 0.2f;
            }
        } else {
            #pragma unroll
            for (int w = 0; w < 8; w++) {
                float ax = 0.f, ay = 0.f, az = 0.f, aw = 0.f;
                #pragma unroll
                for (int s = 0; s < S2_N; s++) {
                    float4 v = *(const float4*)(xt + (size_t)s_nbr[gr * S2_N + s] * IN_F
                                                + f0 + (gw0 + w) * 4);
                    ax += v.x; ay += v.y; az += v.z; aw += v.w;
                }
                int k = (gw0 + w) * 4;
                Zt[(k + 0) * 128 + gr] = ax * 0.5f;
                Zt[(k + 1) * 128 + gr] = ay * 0.5f;
                Zt[(k + 2) * 128 + gr] = az * 0.5f;
                Zt[(k + 3) * 128 + gr] = aw * 0.5f;
            }
        }
        // ---- weight chunk ----
        for (int idx = tid; idx < 64 * 32; idx += 256) {
            int kr = idx >> 5, c4 = idx & 31;
            int kg = kt * 64 + kr;
            const float* srcw = (kg < IN_F) ? (W1s + (size_t)kg * H1_N)
                                            : (W1n + (size_t)(kg - IN_F) * H1_N);
            *(float4*)&Wt[kr * 128 + c4 * 4] = *(const float4*)(srcw + c4 * 4);
        }
        __syncthreads();

        // ---- f32x2 mainloop ----
        #pragma unroll 4
        for (int k = 0; k < 64; k++) {
            const ull* za = (const ull*)&Zt[k * 128 + r0];
            ull a0 = za[0], a1 = za[1], a2 = za[2], a3 = za[3];
            float4 bA = *(const float4*)&Wt[k * 128 + c0];
            float4 bB = *(const float4*)&Wt[k * 128 + c0 + 4];
            ull bd[8];
            bd[0] = dup2(bA.x); bd[1] = dup2(bA.y);
            bd[2] = dup2(bA.z); bd[3] = dup2(bA.w);
            bd[4] = dup2(bB.x); bd[5] = dup2(bB.y);
            bd[6] = dup2(bB.z); bd[7] = dup2(bB.w);
            #pragma unroll
            for (int j = 0; j < 8; j++) {
                acc[0][j] = fma2(a0, bd[j], acc[0][j]);
                acc[1][j] = fma2(a1, bd[j], acc[1][j]);
                acc[2][j] = fma2(a2, bd[j], acc[2][j]);
                acc[3][j] = fma2(a3, bd[j], acc[3][j]);
            }
        }
    }

    // ---- epilogue: u = acc + b1; spike bytes ----
    float bb[8];
    #pragma unroll
    for (int j = 0; j < 8; j++) bb[j] = b1[c0 + j];
    #pragma unroll
    for (int i = 0; i < 4; i++) {
        int row = rowbase + r0 + 2 * i;
        ull pk0 = 0ull, pk1 = 0ull;
        #pragma unroll
        for (int j = 0; j < 8; j++) {
            if (lo2(acc[i][j]) + bb[j] >= 1.0f) pk0 |= (1ull << (8 * j));
            if (hi2(acc[i][j]) + bb[j] >= 1.0f) pk1 |= (1ull << (8 * j));
        }
        *(ull*)(g_s1 + ((size_t)t * R1 + row)     * H1_N + c0) = pk0;
        *(ull*)(g_s1 + ((size_t)t * R1 + row + 1) * H1_N + c0) = pk1;
    }
}

// ============================================================================
// Kernel 2: layer-2 GEMM, packed fp32x2. u2 = [g0 | mean(g1)] @ [W2s;W2n] + b2.
// Block: 64 rows x 64 cols, K=256. Packed-byte summation for the 5-way mean.
// Dyn smem: Zt[256][64] + Wt[256][64] = 128 KB.
// ============================================================================
__global__ void __launch_bounds__(256, 1)
layer2_kernel(const float* __restrict__ W2s, const float* __restrict__ W2n,
              const float* __restrict__ b2) {
    extern __shared__ float sm[];
    float* Zt = sm;                  // [256][64] k-major
    float* Wt = sm + 256 * 64;       // [256][64]
    const int tid = threadIdx.x;
    const int t = blockIdx.y;
    const int b0 = blockIdx.x * 64;

    const uint8_t* s1t = g_s1 + (size_t)t * R1 * H1_N;
    const int r  = tid & 63;
    const int w0 = tid >> 6;
    for (int w = w0; w < 32; w += 4) {
        uint32_t gw = *(const uint32_t*)(s1t + (size_t)(b0 + r) * H1_N + w * 4);
        uint32_t mw = 0;   // bytes are 0/1; sum of 5 fits in a byte
        #pragma unroll
        for (int s = 0; s < S1_N; s++)
            mw += *(const uint32_t*)(s1t + (size_t)(B_N + (b0 + r) * S1_N + s) * H1_N + w * 4);
        int k = w * 4;
        Zt[(k + 0) * 64 + r] = (float)(gw & 0xffu);
        Zt[(k + 1) * 64 + r] = (float)((gw >> 8) & 0xffu);
        Zt[(k + 2) * 64 + r] = (float)((gw >> 16) & 0xffu);
        Zt[(k + 3) * 64 + r] = (float)(gw >> 24);
        Zt[(H1_N + k + 0) * 64 + r] = 0.2f * (float)(mw & 0xffu);
        Zt[(H1_N + k + 1) * 64 + r] = 0.2f * (float)((mw >> 8) & 0xffu);
        Zt[(H1_N + k + 2) * 64 + r] = 0.2f * (float)((mw >> 16) & 0xffu);
        Zt[(H1_N + k + 3) * 64 + r] = 0.2f * (float)(mw >> 24);
    }
    for (int idx = tid; idx < 256 * 16; idx += 256) {
        int kr = idx >> 4, c4 = idx & 15;
        const float* src = (kr < H1_N) ? (W2s + (size_t)kr * H2_N)
                                       : (W2n + (size_t)(kr - H1_N) * H2_N);
        *(float4*)&Wt[kr * 64 + c4 * 4] = *(const float4*)(src + c4 * 4);
    }
    __syncthreads();

    const int r0 = (tid & 15) * 4;
    const int c0 = (tid >> 4) * 4;

    ull acc[2][4];                    // 2 row-pairs x 4 cols
    #pragma unroll
    for (int i = 0; i < 2; i++)
        #pragma unroll
        for (int j = 0; j < 4; j++) acc[i][j] = 0ull;

    #pragma unroll 8
    for (int k = 0; k < 256; k++) {
        const ull* za = (const ull*)&Zt[k * 64 + r0];
        ull a0 = za[0], a1 = za[1];
        float4 b4 = *(const float4*)&Wt[k * 64 + c0];
        ull bd0 = dup2(b4.x), bd1 = dup2(b4.y), bd2 = dup2(b4.z), bd3 = dup2(b4.w);
        acc[0][0] = fma2(a0, bd0, acc[0][0]);
        acc[1][0] = fma2(a1, bd0, acc[1][0]);
        acc[0][1] = fma2(a0, bd1, acc[0][1]);
        acc[1][1] = fma2(a1, bd1, acc[1][1]);
        acc[0][2] = fma2(a0, bd2, acc[0][2]);
        acc[1][2] = fma2(a1, bd2, acc[1][2]);
        acc[0][3] = fma2(a0, bd3, acc[0][3]);
        acc[1][3] = fma2(a1, bd3, acc[1][3]);
    }

    float bb[4];
    #pragma unroll
    for (int j = 0; j < 4; j++) bb[j] = b2[c0 + j];
    #pragma unroll
    for (int i = 0; i < 2; i++) {
        int b = b0 + r0 + 2 * i;
        uint32_t pk0 = 0, pk1 = 0;
        #pragma unroll
        for (int j = 0; j < 4; j++) {
            if (lo2(acc[i][j]) + bb[j] >= 1.0f) pk0 |= (1u << (8 * j));
            if (hi2(acc[i][j]) + bb[j] >= 1.0f) pk1 |= (1u << (8 * j));
        }
        *(uint32_t*)(g_s2 + ((size_t)t * B_N + b)     * H2_N + c0) = pk0;
        *(uint32_t*)(g_s2 + ((size_t)t * B_N + b + 1) * H2_N + c0) = pk1;
    }
}

// ============================================================================
// Kernel 3: readout. out[b,j] = ro_b[j] + sum_c (sum_t s2[t,b,c]*A[c,t]) ro_W[c,j]
// One warp per batch row.
// ============================================================================
__global__ void __launch_bounds__(256)
readout_kernel(const float* __restrict__ ro_W, const float* __restrict__ ro_b,
               float* __restrict__ out) {
    __shared__ float Msm[8][64];
    const int warp = threadIdx.x >> 5;
    const int lane = threadIdx.x & 31;
    const int b = blockIdx.x * 8 + warp;

    float m0 = 0.f, m1 = 0.f;
    #pragma unroll
    for (int t = 0; t < T_STEPS; t++) {
        const uint8_t* row = g_s2 + ((size_t)t * B_N + b) * H2_N;
        m0 = fmaf((float)row[lane],      g_A[lane * T_STEPS + t],        m0);
        m1 = fmaf((float)row[lane + 32], g_A[(lane + 32) * T_STEPS + t], m1);
    }
    Msm[warp][lane] = m0;
    Msm[warp][lane + 32] = m1;
    __syncwarp();

    float o = ro_b[lane];
    #pragma unroll
    for (int c = 0; c < 64; c++)
        o = fmaf(Msm[warp][c], ro_W[c * C_OUT + lane], o);
    out[(size_t)b * C_OUT + lane] = o;
}

// ============================================================================
extern "C" void kernel_launch(void* const* d_in, const int* in_sizes, int n_in,
                              void* d_out, int out_size) {
    const float* x    = (const float*)d_in[0];
    const int*   nodes= (const int*)  d_in[1];
    const int*   nbr1 = (const int*)  d_in[2];
    const int*   nbr2 = (const int*)  d_in[3];
    const float* W1s  = (const float*)d_in[4];
    const float* W1n  = (const float*)d_in[5];
    const float* b1   = (const float*)d_in[6];
    const float* W2s  = (const float*)d_in[7];
    const float* W2n  = (const float*)d_in[8];
    const float* b2   = (const float*)d_in[9];
    const float* dlw  = (const float*)d_in[10];
    const float* dwk  = (const float*)d_in[11];
    const float* roW  = (const float*)d_in[12];
    const float* rob  = (const float*)d_in[13];
    float* out = (float*)d_out;

    cudaFuncSetAttribute(layer1_kernel, cudaFuncAttributeMaxDynamicSharedMemorySize, 65536);
    cudaFuncSetAttribute(layer2_kernel, cudaFuncAttributeMaxDynamicSharedMemorySize, 131072);

    prepA_kernel<<<1, 64>>>(dlw, dwk);
    layer1_kernel<<<dim3(R1 / 128, T_STEPS), 256, 65536>>>(x, nodes, nbr1, nbr2, W1s, W1n, b1);
    layer2_kernel<<<dim3(B_N / 64, T_STEPS), 256, 131072>>>(W2s, W2n, b2);
    readout_kernel<<<B_N / 8, 256>>>(roW, rob, out);
}